// round 1
// baseline (speedup 1.0000x reference)
#include <cuda_runtime.h>

#define NVOX   262144
#define NU     65536
#define C_IN   128
#define C_HID  64
#define K_OUT  20
#define TILE   64
#define NTILES (NVOX / TILE)

// Scratch: rank[v] = position in unmasked_idx, or -1 if masked.
__device__ int g_rank[NVOX];

__global__ void rank_kernel(const int* __restrict__ ui, const int* __restrict__ mi) {
    int t = blockIdx.x * blockDim.x + threadIdx.x;
    if (t < NU)        g_rank[ui[t]]      = t;
    else if (t < NVOX) g_rank[mi[t - NU]] = -1;
}

struct __align__(16) Smem {
    // resident weights
    float w1s [C_IN * C_HID];    // [c][j]
    float w2s [C_HID * C_IN];    // [j][c]
    float sdbs[C_IN * C_HID];    // [c][j]
    float sscs[C_HID * K_OUT];   // [j][k]
    float auxs[C_IN * K_OUT];    // [c][k]
    float b1s[C_HID], lngs[C_HID], lnbs[C_HID], sdbbs[C_HID];
    float b2s[C_IN];
    float sscbs[K_OUT], auxbs[K_OUT];
    // per-tile staging
    float fs[C_IN * TILE];       // [c][v]  feats, then vox (prior written into masked cols)
    float hs[C_HID * TILE];      // [j][v]
    float ds[C_HID * TILE];      // [j][v]
    float mus[TILE], rss[TILE];
    float red1[4 * TILE], red2[4 * TILE];
    int   ranks[TILE];
    int   lstv[TILE], lstr[TILE];
    int   cnt;
};

__global__ void __launch_bounds__(256, 1)
fused_kernel(const float* __restrict__ x3d,
             const float* __restrict__ w1,   const float* __restrict__ b1,
             const float* __restrict__ ln_g, const float* __restrict__ ln_b,
             const float* __restrict__ w2,   const float* __restrict__ b2,
             const float* __restrict__ sdb_w, const float* __restrict__ sdb_b,
             const float* __restrict__ ssc_w, const float* __restrict__ ssc_b,
             const float* __restrict__ aux_w, const float* __restrict__ aux_b,
             float* __restrict__ out)
{
    extern __shared__ char smem_raw[];
    Smem* s = reinterpret_cast<Smem*>(smem_raw);
    const int t = threadIdx.x;

    // ---- one-time weight residency ----
    for (int i = t; i < C_IN * C_HID;  i += 256) s->w1s[i]  = w1[i];
    for (int i = t; i < C_HID * C_IN;  i += 256) s->w2s[i]  = w2[i];
    for (int i = t; i < C_IN * C_HID;  i += 256) s->sdbs[i] = sdb_w[i];
    for (int i = t; i < C_HID * K_OUT; i += 256) s->sscs[i] = ssc_w[i];
    for (int i = t; i < C_IN * K_OUT;  i += 256) s->auxs[i] = aux_w[i];
    if (t < C_HID) { s->b1s[t] = b1[t]; s->lngs[t] = ln_g[t]; s->lnbs[t] = ln_b[t]; s->sdbbs[t] = sdb_b[t]; }
    if (t < C_IN)  { s->b2s[t] = b2[t]; }
    if (t < K_OUT) { s->sscbs[t] = ssc_b[t]; s->auxbs[t] = aux_b[t]; }

    float* outsem = out + (size_t)K_OUT * NVOX;

    const int vg = t & 15;   // voxel group (4 voxels)
    const int g2 = t >> 4;   // output group

    for (int tile = blockIdx.x; tile < NTILES; tile += gridDim.x) {
        const int vbase = tile * TILE;
        __syncthreads();                      // previous tile fully consumed
        if (t == 0) s->cnt = 0;

        // ---- load feats tile [128 c][64 v], fully coalesced float4 ----
        #pragma unroll
        for (int it = 0; it < 8; ++it) {
            int i  = t + it * 256;            // float4 index, 0..2047
            int c  = i >> 4;
            int vq = i & 15;
            *reinterpret_cast<float4*>(&s->fs[c * TILE + vq * 4]) =
                *reinterpret_cast<const float4*>(&x3d[c * NVOX + vbase + vq * 4]);
        }
        if (t < TILE) s->ranks[t] = g_rank[vbase + t];
        __syncthreads();
        if (t < TILE) {
            int r = s->ranks[t];
            if (r >= 0) { int p = atomicAdd(&s->cnt, 1); s->lstv[p] = t; s->lstr[p] = r; }
        }

        // ---- GEMM1: z = feats @ w1 + b1   ([64v][64j], K=128) ----
        {
            float acc[4][4] = {};
            #pragma unroll 4
            for (int c = 0; c < C_IN; ++c) {
                float4 f = *reinterpret_cast<const float4*>(&s->fs[c * TILE + vg * 4]);
                float4 w = *reinterpret_cast<const float4*>(&s->w1s[c * C_HID + g2 * 4]);
                float fa[4] = {f.x, f.y, f.z, f.w};
                float wa[4] = {w.x, w.y, w.z, w.w};
                #pragma unroll
                for (int i = 0; i < 4; ++i)
                    #pragma unroll
                    for (int jj = 0; jj < 4; ++jj)
                        acc[i][jj] += fa[i] * wa[jj];
            }
            #pragma unroll
            for (int jj = 0; jj < 4; ++jj) {
                float b = s->b1s[g2 * 4 + jj];
                float4 o = {acc[0][jj] + b, acc[1][jj] + b, acc[2][jj] + b, acc[3][jj] + b};
                *reinterpret_cast<float4*>(&s->hs[(g2 * 4 + jj) * TILE + vg * 4]) = o;
            }
        }
        __syncthreads();

        // ---- LayerNorm (per voxel over 64 j) + LeakyReLU ----
        {
            int v = t & 63, q = t >> 6;
            float sum = 0.f, ssum = 0.f;
            #pragma unroll
            for (int j = 0; j < 16; ++j) {
                float x = s->hs[(q * 16 + j) * TILE + v];
                sum += x; ssum += x * x;
            }
            s->red1[q * TILE + v] = sum;
            s->red2[q * TILE + v] = ssum;
        }
        __syncthreads();
        if (t < TILE) {
            float sum  = s->red1[t] + s->red1[TILE + t] + s->red1[2 * TILE + t] + s->red1[3 * TILE + t];
            float ssum = s->red2[t] + s->red2[TILE + t] + s->red2[2 * TILE + t] + s->red2[3 * TILE + t];
            float mu  = sum * (1.f / 64.f);
            float var = ssum * (1.f / 64.f) - mu * mu;
            s->mus[t] = mu;
            s->rss[t] = rsqrtf(var + 1e-5f);
        }
        __syncthreads();
        #pragma unroll
        for (int it = 0; it < 16; ++it) {
            int i = t + it * 256;
            int j = i >> 6, v = i & 63;
            float x = s->hs[i];
            x = (x - s->mus[v]) * s->rss[v] * s->lngs[j] + s->lnbs[j];
            s->hs[i] = x > 0.f ? x : 0.01f * x;
        }
        __syncthreads();

        // ---- GEMM2: prior = h @ w2 + b2; overwrite masked columns of fs ----
        {
            float acc[4][8] = {};
            #pragma unroll 2
            for (int j = 0; j < C_HID; ++j) {
                float4 h4 = *reinterpret_cast<const float4*>(&s->hs[j * TILE + vg * 4]);
                float4 wA = *reinterpret_cast<const float4*>(&s->w2s[j * C_IN + g2 * 8]);
                float4 wB = *reinterpret_cast<const float4*>(&s->w2s[j * C_IN + g2 * 8 + 4]);
                float ha[4] = {h4.x, h4.y, h4.z, h4.w};
                float wa[8] = {wA.x, wA.y, wA.z, wA.w, wB.x, wB.y, wB.z, wB.w};
                #pragma unroll
                for (int i = 0; i < 4; ++i)
                    #pragma unroll
                    for (int kk = 0; kk < 8; ++kk)
                        acc[i][kk] += ha[i] * wa[kk];
            }
            #pragma unroll
            for (int i = 0; i < 4; ++i) {
                int v = vg * 4 + i;
                if (s->ranks[v] < 0) {          // masked -> vox = prior
                    #pragma unroll
                    for (int kk = 0; kk < 8; ++kk)
                        s->fs[(g2 * 8 + kk) * TILE + v] = acc[i][kk] + s->b2s[g2 * 8 + kk];
                }
            }
        }
        __syncthreads();

        // ---- GEMM3: d = leaky(vox @ sdb_w + sdb_b)  ([64v][64j], K=128) ----
        {
            float acc[4][4] = {};
            #pragma unroll 4
            for (int c = 0; c < C_IN; ++c) {
                float4 f = *reinterpret_cast<const float4*>(&s->fs[c * TILE + vg * 4]);
                float4 w = *reinterpret_cast<const float4*>(&s->sdbs[c * C_HID + g2 * 4]);
                float fa[4] = {f.x, f.y, f.z, f.w};
                float wa[4] = {w.x, w.y, w.z, w.w};
                #pragma unroll
                for (int i = 0; i < 4; ++i)
                    #pragma unroll
                    for (int jj = 0; jj < 4; ++jj)
                        acc[i][jj] += fa[i] * wa[jj];
            }
            #pragma unroll
            for (int jj = 0; jj < 4; ++jj) {
                float b = s->sdbbs[g2 * 4 + jj];
                float4 o;
                float x0 = acc[0][jj] + b; o.x = x0 > 0.f ? x0 : 0.01f * x0;
                float x1 = acc[1][jj] + b; o.y = x1 > 0.f ? x1 : 0.01f * x1;
                float x2 = acc[2][jj] + b; o.z = x2 > 0.f ? x2 : 0.01f * x2;
                float x3 = acc[3][jj] + b; o.w = x3 > 0.f ? x3 : 0.01f * x3;
                *reinterpret_cast<float4*>(&s->ds[(g2 * 4 + jj) * TILE + vg * 4]) = o;
            }
        }
        __syncthreads();

        // ---- GEMM4: ssc = d @ ssc_w + ssc_b -> out[k*NVOX + v] ----
        {
            int v = t & 63, kq = t >> 6, k0 = kq * 5;
            float acc[5] = {};
            #pragma unroll 4
            for (int j = 0; j < C_HID; ++j) {
                float dv = s->ds[j * TILE + v];
                #pragma unroll
                for (int kk = 0; kk < 5; ++kk)
                    acc[kk] += dv * s->sscs[j * K_OUT + k0 + kk];
            }
            #pragma unroll
            for (int kk = 0; kk < 5; ++kk)
                out[(size_t)(k0 + kk) * NVOX + vbase + v] = acc[kk] + s->sscbs[k0 + kk];
        }

        // ---- AUX head: sem = feats[unmasked] @ aux_w + aux_b ----
        // fs columns of unmasked voxels are untouched original feats.
        {
            int nu = s->cnt;
            for (int i = t; i < nu * K_OUT; i += 256) {
                int ul = i / K_OUT;
                int k  = i - ul * K_OUT;
                int v  = s->lstv[ul];
                float a = s->auxbs[k];
                #pragma unroll 4
                for (int c = 0; c < C_IN; ++c)
                    a += s->fs[c * TILE + v] * s->auxs[c * K_OUT + k];
                outsem[(size_t)s->lstr[ul] * K_OUT + k] = a;
            }
        }
    }
}

extern "C" void kernel_launch(void* const* d_in, const int* in_sizes, int n_in,
                              void* d_out, int out_size)
{
    const float* x3d   = (const float*)d_in[0];
    const float* w1    = (const float*)d_in[1];
    const float* b1    = (const float*)d_in[2];
    const float* ln_g  = (const float*)d_in[3];
    const float* ln_b  = (const float*)d_in[4];
    const float* w2    = (const float*)d_in[5];
    const float* b2    = (const float*)d_in[6];
    const float* sdb_w = (const float*)d_in[7];
    const float* sdb_b = (const float*)d_in[8];
    const float* ssc_w = (const float*)d_in[9];
    const float* ssc_b = (const float*)d_in[10];
    const float* aux_w = (const float*)d_in[11];
    const float* aux_b = (const float*)d_in[12];
    const int* ui      = (const int*)d_in[13];
    const int* mi      = (const int*)d_in[14];
    float* out         = (float*)d_out;

    int nsm = 0;
    cudaDeviceGetAttribute(&nsm, cudaDevAttrMultiProcessorCount, 0);
    if (nsm <= 0) nsm = 148;

    cudaFuncSetAttribute(fused_kernel,
                         cudaFuncAttributeMaxDynamicSharedMemorySize,
                         (int)sizeof(Smem));

    rank_kernel<<<NVOX / 256, 256>>>(ui, mi);
    fused_kernel<<<nsm, 256, sizeof(Smem)>>>(x3d, w1, b1, ln_g, ln_b, w2, b2,
                                             sdb_w, sdb_b, ssc_w, ssc_b,
                                             aux_w, aux_b, out);
}